// round 12
// baseline (speedup 1.0000x reference)
#include <cuda_runtime.h>

// MeshfreeKANNet: u[m] = (sum_n phi_win[m,n]*w[n]) / (sum_n phi_win[m,n] + 1e-10)
// R12: grid was parallelism-starved (4096 warps, occ ceiling 43%). Split each
// point across SPLIT=2 warps (512 nodes, ~36 hits each). With the ILP-2
// phase-2 loop each warp does ONE double-pipeline pass -> total issued work
// per point identical to R11, but 8192 warps -> ~50% occupancy at 4 blk/SM.
// Per-pair math bit-identical to R5/R11; only summation grouping changes
// (half0 + half1 per point, fixed order, deterministic).

#define MM      4096
#define NN      1024
#define HIDN    8
#define SPLIT   2
#define WARPS   8
#define PPB     (WARPS / SPLIT)    // 4 points per block
#define THREADS 256
#define BLOCKS  (MM / PPB)         // 1024
#define NH      (NN / SPLIT)       // 512 nodes per warp

#define R2_F     0.09f
#define INV_R    (1.0f / 0.3f)
#define INV_H    (1.0f / 0.75f)

typedef float4 f4;

// One pair's KAN evaluation. Bit-exact R5 math.
__device__ __forceinline__ float pair_phi(float dx, float dy,
                                          const f4 (*s_Wp)[4])
{
    const float gridv[5] = {-1.5f, -0.75f, 0.0f, 0.75f, 1.5f};
    const float d2 = fmaf(dx, dx, dy * dy);
    const float kx = dx * INV_R;
    const float ky = dy * INV_R;

    float ba[5], bb[5];
    #pragma unroll
    for (int s = 0; s < 5; s++) {
        ba[s] = fmaxf(0.0f, 1.0f - fabsf(kx - gridv[s]) * INV_H);
        bb[s] = fmaxf(0.0f, 1.0f - fabsf(ky - gridv[s]) * INV_H);
    }

    float phi_raw = 0.0f;
    #pragma unroll 2
    for (int h = 0; h < HIDN; h++) {
        const f4 q0 = s_Wp[h][0];
        const f4 q1 = s_Wp[h][1];
        const f4 q2 = s_Wp[h][2];
        const f4 q3 = s_Wp[h][3];
        const float wa[5]  = {q0.x, q0.y, q0.z, q0.w, q1.x};
        const float wb[5]  = {q1.y, q1.z, q1.w, q2.x, q2.y};
        const float w2r[5] = {q2.z, q2.w, q3.x, q3.y, q3.z};

        float hv = 0.0f;
        #pragma unroll
        for (int s = 0; s < 5; s++) {
            hv = fmaf(ba[s], wa[s], hv);
            hv = fmaf(bb[s], wb[s], hv);
        }
        #pragma unroll
        for (int s = 0; s < 5; s++) {
            const float bh = fmaxf(0.0f, 1.0f - fabsf(hv - gridv[s]) * INV_H);
            phi_raw = fmaf(bh, w2r[s], phi_raw);
        }
    }

    const float q = sqrtf(d2) * INV_R;
    const float win = fmaf(q * q, fmaf(fmaf(-3.0f, q, 8.0f), q, -6.0f), 1.0f);
    return phi_raw * win;
}

__global__ __launch_bounds__(THREADS, 4)
void meshfree_kan_kernel(const float* __restrict__ x,
                         const float* __restrict__ nodes,
                         const float* __restrict__ W1a,
                         const float* __restrict__ W1b,
                         const float* __restrict__ W2,
                         const float* __restrict__ w,
                         float* __restrict__ out)
{
    __shared__ float2 s_nxy[NN];
    __shared__ float  s_w[NN];
    __shared__ f4     s_Wp[HIDN][4];   // {W1a[h][0..4], W1b[h][0..4], W2[h][0..4], 0}
    __shared__ unsigned short s_buf[WARPS][NH];
    __shared__ float  s_S[WARPS], s_Sw[WARPS];

    const int tid = threadIdx.x;
    const int m0  = blockIdx.x * PPB;

    for (int i = tid; i < NN; i += THREADS) {
        s_nxy[i] = ((const float2*)nodes)[i];
        s_w[i]   = w[i];
    }
    if (tid < HIDN * 16) {
        const int h = tid >> 4;
        const int e = tid & 15;
        float v = 0.0f;
        if (e < 5)       v = W1a[h * 5 + e];
        else if (e < 10) v = W1b[h * 5 + (e - 5)];
        else if (e < 15) v = W2 [h * 5 + (e - 10)];
        ((float*)s_Wp)[tid] = v;
    }
    __syncthreads();

    const int warp = tid >> 5;
    const int lane = tid & 31;
    const int p    = warp >> 1;          // point within block (0..3)
    const int half = warp & 1;           // node half-range
    const int m    = m0 + p;

    const float px = x[2 * m];
    const float py = x[2 * m + 1];

    // ---- Phase 1: distance filter + warp stream compaction (own half) ----
    int cnt = 0;
    const unsigned lmask = (1u << lane) - 1u;
    const int b0 = half * NH;
    #pragma unroll 4
    for (int base = b0; base < b0 + NH; base += 32) {
        const int n = base + lane;
        const float2 nd = s_nxy[n];
        const float dx = px - nd.x;
        const float dy = py - nd.y;
        const float d2 = fmaf(dx, dx, dy * dy);
        const bool hit = (d2 <= R2_F);
        const unsigned msk = __ballot_sync(0xffffffffu, hit);
        if (hit) s_buf[warp][cnt + __popc(msk & lmask)] = (unsigned short)n;
        cnt += __popc(msk);
    }
    __syncwarp();

    // ---- Phase 2: two independent pair pipelines per lane ----
    float S = 0.0f, Sw = 0.0f;
    for (int i = lane; i < cnt; i += 64) {
        const int iB = i + 32;
        const bool hasB = (iB < cnt);

        const int nA = (int)s_buf[warp][i];
        const float2 ndA = s_nxy[nA];
        const float phiA = pair_phi(px - ndA.x, py - ndA.y, s_Wp);

        float phiB = 0.0f;
        int nB = 0;
        if (hasB) {
            nB = (int)s_buf[warp][iB];
            const float2 ndB = s_nxy[nB];
            phiB = pair_phi(px - ndB.x, py - ndB.y, s_Wp);
        }

        S  += phiA;
        Sw  = fmaf(phiA, s_w[nA], Sw);
        if (hasB) {
            S  += phiB;
            Sw  = fmaf(phiB, s_w[nB], Sw);
        }
    }

    // ---- Warp reduction ----
    #pragma unroll
    for (int o = 16; o > 0; o >>= 1) {
        S  += __shfl_xor_sync(0xffffffffu, S,  o);
        Sw += __shfl_xor_sync(0xffffffffu, Sw, o);
    }
    if (lane == 0) { s_S[warp] = S; s_Sw[warp] = Sw; }
    __syncthreads();

    // ---- Combine the two half-range partials per point (fixed order) ----
    if (tid < PPB) {
        const float St  = s_S [2 * tid] + s_S [2 * tid + 1];
        const float Swt = s_Sw[2 * tid] + s_Sw[2 * tid + 1];
        out[m0 + tid] = Swt / (St + 1e-10f);
    }
}

extern "C" void kernel_launch(void* const* d_in, const int* in_sizes, int n_in,
                              void* d_out, int out_size)
{
    const float* x     = (const float*)d_in[0];   // [4096, 2]
    const float* nodes = (const float*)d_in[1];   // [1024, 2]
    const float* W1a   = (const float*)d_in[2];   // [8, 5]
    const float* W1b   = (const float*)d_in[3];   // [8, 5]
    const float* W2    = (const float*)d_in[4];   // [1, 40]
    const float* w     = (const float*)d_in[5];   // [1024, 1]
    float* out = (float*)d_out;                   // [4096, 1]

    meshfree_kan_kernel<<<BLOCKS, THREADS>>>(x, nodes, W1a, W1b, W2, w, out);
}